// round 17
// baseline (speedup 1.0000x reference)
#include <cuda_runtime.h>
#include <cuda_fp16.h>
#include <cstdint>

#define NN  100000
#define NE  1600000
#define NG  512
#define LL  1000
#define FXD 4
#define FXT 5
#define H   64
#define H2  128
#define NOUT 2
#define NBLK 98          // scan blocks (one wave, <=148 SMs)
#define BUCKB (NE / 256) // 6250 bucket blocks
#define HISTB ((NE + 1023) / 1024)   // hist blocks (4 edges/thread)

// ---------------- scratch (zero at load; k_final re-zeroes what must be zero) ----------------
__device__ int    d_cnt[NN];           // in-degree (edges only; +1 self added logically)
__device__ int    d_off[NN];           // CSR offsets (incl. self)
__device__ int    d_cur[NN];           // bucket cursors
__device__ int    d_bsum[NBLK];        // block totals; nonzero doubles as ready flag
__device__ int    d_scan_fin;          // scan-completion counter
__device__ int    d_src[NE + NN];      // CSR source list (self at off[i], edges after)
__device__ float  d_dis[NN];
__device__ float4 d_xs[NN];            // dis[i] * x[i]
__device__ __half d_h1s[NN * H];       // dis[i] * relu-h1[i], fp16
__device__ int    d_gbits[NG * H2];    // pooled max(h2) as ordered int bits
__device__ float  d_tmax[NG * H];      // conv1d branch pooled output

__device__ __forceinline__ unsigned long long fma2(unsigned long long a,
                                                   unsigned long long b,
                                                   unsigned long long c) {
    unsigned long long d;
    asm("fma.rn.f32x2 %0, %1, %2, %3;" : "=l"(d) : "l"(a), "l"(b), "l"(c));
    return d;
}
__device__ __forceinline__ unsigned long long pack2(float a, float b) {
    unsigned long long d;
    asm("mov.b64 %0, {%1,%2};" : "=l"(d) : "f"(a), "f"(b));
    return d;
}
__device__ __forceinline__ float2 unpack2(unsigned long long a) {
    float2 r;
    asm("mov.b64 {%0,%1}, %2;" : "=f"(r.x), "=f"(r.y) : "l"(a));
    return r;
}

// ---------------- K1: blocks [0,NG): conv1d branch; blocks [NG,...): degree histogram ----
__global__ void k_histconv(const int* __restrict__ ei,
                           const float* __restrict__ target,
                           const float* __restrict__ Wc, const float* __restrict__ bc) {
    __shared__ __align__(16) char s_raw[25088];
    int tid = threadIdx.x;                    // 256

    if (blockIdx.x >= NG) {
        // ---- histogram: 4 edges per thread over the col half of ei ----
        int e = (blockIdx.x - NG) * 1024 + tid * 4;
        if (e + 4 <= NE) {
            int4 c4 = *(const int4*)(ei + NE + e);
            atomicAdd(&d_cnt[c4.x], 1);
            atomicAdd(&d_cnt[c4.y], 1);
            atomicAdd(&d_cnt[c4.z], 1);
            atomicAdd(&d_cnt[c4.w], 1);
        } else {
            for (int k = 0; k < 4 && e + k < NE; k++)
                atomicAdd(&d_cnt[ei[NE + e + k]], 1);
        }
        return;
    }

    // ---- conv1d branch ----
    float (*sh)[6] = (float(*)[6])s_raw;          // [LL][6], col 5 = zero pad
    float* red = (float*)(s_raw + 24000);         // [256]
    int g = blockIdx.x;
    const float* tg = target + (size_t)g * LL * FXT;
    for (int idx = tid; idx < LL * FXT; idx += 256) {
        int l = idx / FXT, i = idx - l * FXT;
        sh[l][i] = tg[idx];
    }
    for (int l = tid; l < LL; l += 256) sh[l][5] = 0.f;
    __syncthreads();

    int c   = tid & 63;
    int seg = tid >> 6;
    unsigned long long wk[3][3];
#pragma unroll
    for (int k = 0; k < 3; k++)
#pragma unroll
        for (int p = 0; p < 3; p++) {
            float w0 = Wc[c * 15 + (2 * p) * 3 + k];
            float w1 = (p < 2) ? Wc[c * 15 + (2 * p + 1) * 3 + k] : 0.f;
            wk[k][p] = pack2(w0, w1);
        }

    int start = seg * 250;
    int end = (seg == 3) ? (LL - 2) : (start + 250);
    float m = -3.4e38f;
    for (int l = start; l < end; l++) {
        unsigned long long a0 = 0ull, a1 = 0ull, a2 = 0ull;
#pragma unroll
        for (int k = 0; k < 3; k++) {
            const unsigned long long* row = (const unsigned long long*)&sh[l + k][0];
            a0 = fma2(row[0], wk[k][0], a0);
            a1 = fma2(row[1], wk[k][1], a1);
            a2 = fma2(row[2], wk[k][2], a2);
        }
        float2 f0 = unpack2(a0), f1 = unpack2(a1), f2 = unpack2(a2);
        m = fmaxf(m, (f0.x + f0.y) + (f1.x + f1.y) + (f2.x + f2.y));
    }
    red[tid] = m;
    __syncthreads();
    if (seg == 0) {
        m = fmaxf(fmaxf(red[c], red[64 + c]), fmaxf(red[128 + c], red[192 + c]));
        m += bc[c];
        d_tmax[g * H + c] = fmaxf(m, 0.f);
    }
}

// ---------------- K2: blocks [0,NBLK): decoupled-lookback scan; rest: bucket (spin) ----
__global__ void k_scanbucket(const int* __restrict__ ei, const float* __restrict__ x) {
    int tid = threadIdx.x;                    // 256

    if (blockIdx.x < NBLK) {
        // ---- scan portion: offsets, cursors, self entry, dis, xs ----
        __shared__ int tsum[256];
        __shared__ int sh_base;
        int b = blockIdx.x;
        int base4 = b * 1024 + tid * 4;
        int loc[4]; int s = 0;
#pragma unroll
        for (int k = 0; k < 4; k++) {
            int i = base4 + k;
            int v = (i < NN) ? (d_cnt[i] + 1) : 0;
            loc[k] = s; s += v;
        }
        tsum[tid] = s; __syncthreads();
        for (int o = 1; o < 256; o <<= 1) {
            int y = (tid >= o) ? tsum[tid - o] : 0;
            __syncthreads();
            tsum[tid] += y;
            __syncthreads();
        }
        if (tid == 0) *(volatile int*)&d_bsum[b] = tsum[255];   // nonzero (>=1024)
        if (tid < 32) {
            int acc = 0;
            for (int p = tid; p < b; p += 32) {
                int v;
                do { v = *(volatile int*)&d_bsum[p]; } while (v == 0);
                acc += v;
            }
#pragma unroll
            for (int o = 16; o; o >>= 1) acc += __shfl_xor_sync(0xffffffffu, acc, o);
            if (tid == 0) sh_base = acc;
        }
        __syncthreads();
        int start = sh_base + tsum[tid] - s;
#pragma unroll
        for (int k = 0; k < 4; k++) {
            int i = base4 + k;
            if (i < NN) {
                int o = start + loc[k];
                d_off[i] = o;
                d_cur[i] = o + 1;             // edges go after the self entry
                d_src[o] = i;                 // self loop
                float di = rsqrtf((float)(d_cnt[i] + 1));
                d_dis[i] = di;
                float4 xv = ((const float4*)x)[i];
                d_xs[i] = make_float4(di * xv.x, di * xv.y, di * xv.z, di * xv.w);
            }
        }
        // signal completion
        __syncthreads();
        if (tid == 0) {
            __threadfence();
            atomicAdd(&d_scan_fin, 1);
        }
        return;
    }

    // ---- bucket portion: wait for scan, then scatter 256 edges ----
    if (tid == 0) {
        while (*(volatile int*)&d_scan_fin < NBLK) __nanosleep(128);
    }
    __syncthreads();
    int e = (blockIdx.x - NBLK) * 256 + tid;
    if (e < NE) {
        int r = ei[e];
        int c = ei[NE + e];
        int pos = atomicAdd(&d_cur[c], 1);
        d_src[pos] = r;
    }
}

// ---------------- K3: layer-1 gather + W1 GEMM + relu, store h1s fp16 ----------------
// 4 lanes per node, 8 nodes per warp, 64 nodes per block.
__global__ void k_aggx_h1(const float* __restrict__ W1, const float* __restrict__ b1) {
    __shared__ float W1s[FXD][H];
    __shared__ float b1s[H];
    int tid = threadIdx.x;                    // 256
    if (tid < FXD * H) W1s[tid >> 6][tid & 63] = W1[tid];
    if (tid < H) b1s[tid] = b1[tid];
    __syncthreads();

    int w = tid >> 5;
    int lane = tid & 31;
    int grp = lane >> 2;                      // node group within warp (0..7)
    int sub = lane & 3;                       // lane within group
    int i = blockIdx.x * 64 + w * 8 + grp;    // node

    float4 acc = make_float4(0.f, 0.f, 0.f, 0.f);
    int off = 0, cnt = 0;
    if (i < NN) { off = d_off[i]; cnt = d_cnt[i] + 1; }
    for (int j = sub; j < cnt; j += 4) {
        int r = d_src[off + j];
        float4 t = d_xs[r];
        acc.x += t.x; acc.y += t.y; acc.z += t.z; acc.w += t.w;
    }
#pragma unroll
    for (int o = 1; o <= 2; o <<= 1) {
        acc.x += __shfl_xor_sync(0xffffffffu, acc.x, o);
        acc.y += __shfl_xor_sync(0xffffffffu, acc.y, o);
        acc.z += __shfl_xor_sync(0xffffffffu, acc.z, o);
        acc.w += __shfl_xor_sync(0xffffffffu, acc.w, o);
    }
    if (i >= NN) return;
    float di = d_dis[i];
    float4 v = make_float4(di * acc.x, di * acc.y, di * acc.z, di * acc.w);

    __half2 outh[8];
    int fb = sub * 16;
#pragma unroll
    for (int t = 0; t < 8; t++) {
        int f = fb + 2 * t;
        float h0 = b1s[f]   + v.x * W1s[0][f]   + v.y * W1s[1][f]   + v.z * W1s[2][f]   + v.w * W1s[3][f];
        float h1 = b1s[f+1] + v.x * W1s[0][f+1] + v.y * W1s[1][f+1] + v.z * W1s[2][f+1] + v.w * W1s[3][f+1];
        h0 = fmaxf(h0, 0.f) * di;
        h1 = fmaxf(h1, 0.f) * di;
        outh[t] = __floats2half2_rn(h0, h1);
    }
    uint4* dst = (uint4*)(d_h1s + (size_t)i * H + fb);
    dst[0] = ((const uint4*)outh)[0];
    dst[1] = ((const uint4*)outh)[1];
}

// ---------------- K4: layer-2 gather + W2 GEMM + pooled max (16 nodes/block) ----------
// Phase 1: 2 edges per load inst (lanes 0-15 edge t, lanes 16-31 edge t+1), LDG.64 rows.
__global__ void k_fused(const float* __restrict__ W2, const float* __restrict__ b2,
                        const int* __restrict__ batch) {
    __shared__ __align__(16) float vt[H][20];   // [k][node], 16 nodes + pad
    int tid = threadIdx.x;                      // 256
    int i0 = blockIdx.x * 16;                   // 6250 blocks

    {   // phase 1
        int w = tid >> 5;
        int lane = tid & 31;
        int hi = lane >> 4;                     // 0/1: even/odd edge of the pair
        int l16 = lane & 15;                    // covers features [4*l16, 4*l16+4)
        const uint2* h1u = (const uint2*)d_h1s; // node row = 16 uint2 (64 halves)
#pragma unroll
        for (int sub = 0; sub < 2; sub++) {
            int n = w * 2 + sub;
            int i = i0 + n;
            int off = d_off[i];
            int cnt = d_cnt[i] + 1;
            float a0 = 0.f, a1 = 0.f, a2 = 0.f, a3 = 0.f;
            float c0 = 0.f, c1 = 0.f, c2 = 0.f, c3 = 0.f;
            int t = 0;
            for (; t + 4 <= cnt; t += 4) {
                int rA = __ldg(&d_src[off + t + hi]);
                int rB = __ldg(&d_src[off + t + 2 + hi]);
                uint2 hA = __ldg(&h1u[rA * 16 + l16]);
                uint2 hB = __ldg(&h1u[rB * 16 + l16]);
                float2 fA0 = __half22float2(*(const __half2*)&hA.x);
                float2 fA1 = __half22float2(*(const __half2*)&hA.y);
                float2 fB0 = __half22float2(*(const __half2*)&hB.x);
                float2 fB1 = __half22float2(*(const __half2*)&hB.y);
                a0 += fA0.x; a1 += fA0.y; a2 += fA1.x; a3 += fA1.y;
                c0 += fB0.x; c1 += fB0.y; c2 += fB1.x; c3 += fB1.y;
            }
            for (; t < cnt; t += 2) {
                int idx = t + hi;
                if (idx < cnt) {
                    int r = __ldg(&d_src[off + idx]);
                    uint2 hv = __ldg(&h1u[r * 16 + l16]);
                    float2 f0 = __half22float2(*(const __half2*)&hv.x);
                    float2 f1 = __half22float2(*(const __half2*)&hv.y);
                    a0 += f0.x; a1 += f0.y; a2 += f1.x; a3 += f1.y;
                }
            }
            a0 += c0; a1 += c1; a2 += c2; a3 += c3;
            a0 += __shfl_xor_sync(0xffffffffu, a0, 16);
            a1 += __shfl_xor_sync(0xffffffffu, a1, 16);
            a2 += __shfl_xor_sync(0xffffffffu, a2, 16);
            a3 += __shfl_xor_sync(0xffffffffu, a3, 16);
            if (hi == 0) {
                float di = d_dis[i];
                int kb = 4 * l16;
                vt[kb][n]     = di * a0;
                vt[kb + 1][n] = di * a1;
                vt[kb + 2][n] = di * a2;
                vt[kb + 3][n] = di * a3;
            }
        }
    }
    __syncthreads();

    // phase 2: GEMM, f = tid&127, half = tid>>7 handles 8 nodes
    int f = tid & 127;
    int half = tid >> 7;
    float bb = b2[f];
    unsigned long long a01 = pack2(bb, bb), a23 = a01, a45 = a01, a67 = a01;
#pragma unroll
    for (int k = 0; k < H; k++) {
        float wv = __ldg(&W2[k * H2 + f]);
        unsigned long long wd = pack2(wv, wv);
        const ulonglong2* P = (const ulonglong2*)&vt[k][half * 8];
        ulonglong2 p0 = P[0];
        ulonglong2 p1 = P[1];
        a01 = fma2(p0.x, wd, a01);
        a23 = fma2(p0.y, wd, a23);
        a45 = fma2(p1.x, wd, a45);
        a67 = fma2(p1.y, wd, a67);
    }
    float2 r01 = unpack2(a01), r23 = unpack2(a23), r45 = unpack2(a45), r67 = unpack2(a67);
    float h[8] = { r01.x, r01.y, r23.x, r23.y, r45.x, r45.y, r67.x, r67.y };

    int bA = batch[i0];
    int bB = batch[i0 + 15];
    float mA = -1.f, mB = -1.f;
#pragma unroll
    for (int n = 0; n < 8; n++) {
        float hv = fmaxf(h[n], 0.f);
        if (batch[i0 + half * 8 + n] == bA) mA = fmaxf(mA, hv); else mB = fmaxf(mB, hv);
    }
    atomicMax(&d_gbits[bA * H2 + f], __float_as_int(mA));   // -1 bits are negative: no-op
    if (bB != bA) atomicMax(&d_gbits[bB * H2 + f], __float_as_int(mB));
}

// ---------------- K5: fused final MLPs + scratch re-zero for graph replay ----------------
__global__ void k_final(const float* __restrict__ Wg, const float* __restrict__ bg,
                        const float* __restrict__ Wt, const float* __restrict__ bt,
                        const float* __restrict__ Wf, const float* __restrict__ bf,
                        const float* __restrict__ Wo, const float* __restrict__ bo,
                        float* __restrict__ out) {
    __shared__ float sg[H2], st[H], sxc[H2], sy[H];
    int g = blockIdx.x;
    int f = threadIdx.x;                    // 64
    sg[f]      = __int_as_float(d_gbits[g * H2 + f]);
    sg[H + f]  = __int_as_float(d_gbits[g * H2 + H + f]);
    st[f]      = d_tmax[g * H + f];
    // re-zero own gbits slice for next replay (only this block reads it)
    d_gbits[g * H2 + f] = 0;
    d_gbits[g * H2 + H + f] = 0;
    // re-zero d_cnt strided, scan flags/counter for next replay
    for (int i = g * 64 + f; i < NN; i += NG * 64) d_cnt[i] = 0;
    {
        int gi = g * 64 + f;
        if (gi < NBLK) d_bsum[gi] = 0;
        if (g == 0 && f == 0) d_scan_fin = 0;
    }
    __syncthreads();

    float gg = bg[f];
#pragma unroll 8
    for (int j = 0; j < H2; j++) gg += sg[j] * Wg[j * H + f];
    float tt = bt[f];
#pragma unroll 8
    for (int j = 0; j < H; j++) tt += st[j] * Wt[j * H + f];
    sxc[f] = gg;
    sxc[H + f] = tt;
    __syncthreads();

    float y = bf[f];
#pragma unroll 8
    for (int j = 0; j < H2; j++) y += sxc[j] * Wf[j * H + f];
    sy[f] = fmaxf(y, 0.f);
    __syncthreads();

    if (f < NOUT) {
        float o = bo[f];
#pragma unroll 8
        for (int j = 0; j < H; j++) o += sy[j] * Wo[j * NOUT + f];
        out[g * NOUT + f] = o;
    }
}

// ---------------- launch ----------------
extern "C" void kernel_launch(void* const* d_in, const int* in_sizes, int n_in,
                              void* d_out, int out_size) {
    const float* x      = (const float*)d_in[0];
    const int*   ei     = (const int*)d_in[1];
    const int*   batch  = (const int*)d_in[2];
    const float* target = (const float*)d_in[3];
    const float* W1 = (const float*)d_in[4];
    const float* b1 = (const float*)d_in[5];
    const float* W2 = (const float*)d_in[6];
    const float* b2 = (const float*)d_in[7];
    const float* Wg = (const float*)d_in[8];
    const float* bg = (const float*)d_in[9];
    const float* Wc = (const float*)d_in[10];
    const float* bc = (const float*)d_in[11];
    const float* Wt = (const float*)d_in[12];
    const float* bt = (const float*)d_in[13];
    const float* Wf = (const float*)d_in[14];
    const float* bf = (const float*)d_in[15];
    const float* Wo = (const float*)d_in[16];
    const float* bo = (const float*)d_in[17];
    float* out = (float*)d_out;

    k_histconv<<<NG + HISTB, 256>>>(ei, target, Wc, bc);
    k_scanbucket<<<NBLK + BUCKB, 256>>>(ei, x);
    k_aggx_h1<<<(NN + 63) / 64, 256>>>(W1, b1);
    k_fused<<<NN / 16, 256>>>(W2, b2, batch);
    k_final<<<NG, 64>>>(Wg, bg, Wt, bt, Wf, bf, Wo, bo, out);
}